// round 1
// baseline (speedup 1.0000x reference)
#include <cuda_runtime.h>
#include <math.h>

// Problem constants
constexpr int Bc   = 2;
constexpr int Lc   = 1000;
constexpr int Dc   = 288;
constexpr int Hc   = 8;
constexpr int DIMc = 36;
constexpr int DFFc = 576;
constexpr int KSc  = 250;
constexpr int NQc  = 250;
constexpr int BHc  = Bc * Hc;      // 16
constexpr int Mrows = Bc * Lc;     // 2000

// Scratch (static device globals; no allocation)
__device__ float g_qf[BHc * Lc * DIMc];
__device__ float g_kf[BHc * Lc * DIMc];
__device__ float g_vf[BHc * Lc * DIMc];
__device__ float g_measure[BHc * Lc];
__device__ int   g_idxq[BHc * NQc];
__device__ float g_sim[BHc * NQc * Lc];          // raw sim -> probabilities (in place)
__device__ float g_av[2 * BHc * NQc * DIMc];     // split-k slabs
__device__ float g_vmean[BHc * DIMc];
__device__ float g_attn[Bc * Lc * Dc];
__device__ float g_h1f[Bc * Lc * Dc];
__device__ float g_f1f[Bc * Lc * DFFc];
__device__ float g_f2f[Bc * Lc * Dc];

__device__ __forceinline__ float gelu_exact(float x) {
    return 0.5f * x * (1.0f + erff(x * 0.7071067811865475f));
}

// ---------------------------------------------------------------------------
// Generic tiled GEMM: C[M,N] = A[M,K] @ W^T (+bias, epilogue per MODE)
// MODE 0: QKV (N=864 : Wq|Wk|Wv), scatter to g_qf/g_kf/g_vf in [bh][l][d]
// MODE 1: FFN1: A=g_h1f, gelu -> g_f1f
// MODE 2: FFN2: A=g_f1f, gelu -> g_f2f
// BM=BN=64, BK=16, 256 threads, 4x4 register tile per thread.
// ---------------------------------------------------------------------------
template <int MODE>
__global__ void __launch_bounds__(256) gemm_tiled(
    const float* __restrict__ A_in, int M, int N, int K,
    const float* __restrict__ W0, const float* __restrict__ W1p,
    const float* __restrict__ W2p,
    const float* __restrict__ b0, const float* __restrict__ b1p,
    const float* __restrict__ b2p)
{
    const float* A = (MODE == 0) ? A_in : (MODE == 1 ? g_h1f : g_f1f);

    __shared__ float As[16][68];
    __shared__ float Bs[16][68];

    const int m0 = blockIdx.y * 64;
    const int n0 = blockIdx.x * 64;
    const int tid = threadIdx.x;
    const int tx = tid & 15;   // column quad
    const int ty = tid >> 4;   // row quad

    float acc[4][4];
#pragma unroll
    for (int i = 0; i < 4; i++)
#pragma unroll
        for (int j = 0; j < 4; j++) acc[i][j] = 0.0f;

    const int ktiles = K / 16;
    for (int kt = 0; kt < ktiles; kt++) {
        const int k0 = kt * 16;
#pragma unroll
        for (int p = 0; p < 4; p++) {
            int t  = tid + p * 256;
            int kk = t & 15;
            int mi = t >> 4;
            // A tile
            int r = m0 + mi;
            As[kk][mi] = (r < M) ? A[r * K + k0 + kk] : 0.0f;
            // W tile (row n0+mi of the [N,K] weight)
            int col = n0 + mi;
            float wv = 0.0f;
            if (col < N) {
                if (MODE == 0) {
                    const float* w;
                    int cc;
                    if (col < 288)      { w = W0;  cc = col; }
                    else if (col < 576) { w = W1p; cc = col - 288; }
                    else                { w = W2p; cc = col - 576; }
                    wv = w[cc * K + k0 + kk];
                } else {
                    wv = W0[col * K + k0 + kk];
                }
            }
            Bs[kk][mi] = wv;
        }
        __syncthreads();
#pragma unroll
        for (int kk = 0; kk < 16; kk++) {
            float4 av4 = *(const float4*)&As[kk][ty * 4];
            float4 bv4 = *(const float4*)&Bs[kk][tx * 4];
            float ar[4] = {av4.x, av4.y, av4.z, av4.w};
            float br[4] = {bv4.x, bv4.y, bv4.z, bv4.w};
#pragma unroll
            for (int i = 0; i < 4; i++)
#pragma unroll
                for (int j = 0; j < 4; j++) acc[i][j] += ar[i] * br[j];
        }
        __syncthreads();
    }

    // epilogue
#pragma unroll
    for (int i = 0; i < 4; i++) {
        int r = m0 + ty * 4 + i;
        if (r >= M) continue;
#pragma unroll
        for (int j = 0; j < 4; j++) {
            int col = n0 + tx * 4 + j;
            if (col >= N) continue;
            float v = acc[i][j];
            if (MODE == 0) {
                int sec, cc;
                const float* bias;
                float* dst;
                if (col < 288)      { sec = 0; cc = col;       bias = b0;  dst = g_qf; }
                else if (col < 576) { sec = 1; cc = col - 288; bias = b1p; dst = g_kf; }
                else                { sec = 2; cc = col - 576; bias = b2p; dst = g_vf; }
                (void)sec;
                v += bias[cc];
                int h  = cc / 36;
                int dd = cc - h * 36;
                int bb = r / Lc;
                int ll = r - bb * Lc;
                dst[((bb * Hc + h) * Lc + ll) * DIMc + dd] = v;
            } else {
                v += b0 == nullptr ? 0.0f : 0.0f; // keep compiler calm
                v = acc[i][j] + b1p[col];
                v = gelu_exact(v);
                if (MODE == 1) g_f1f[r * N + col] = v;
                else           g_f2f[r * N + col] = v;
            }
        }
    }
}

// ---------------------------------------------------------------------------
// Measure kernel: measure[bh][l] = max_j q.k[idx] - sum_j(q.k[idx]) / L
// K[bh] staged in dynamic smem (stride 37 to decorrelate banks).
// grid (16 chunks, 16 bh), 256 threads, warp-per-query.
// ---------------------------------------------------------------------------
__global__ void __launch_bounds__(256) measure_kernel(const int* __restrict__ ik)
{
    extern __shared__ float ks[];   // [Lc][37]
    const int chunk = blockIdx.x;
    const int bh    = blockIdx.y;
    const int tid   = threadIdx.x;

    const float* ksrc = &g_kf[bh * Lc * DIMc];
    for (int i = tid; i < Lc * DIMc; i += 256) {
        int l = i / DIMc;
        int d = i - l * DIMc;
        ks[l * 37 + d] = ksrc[i];
    }
    __syncthreads();

    const int warp = tid >> 5;
    const int lane = tid & 31;
    const int lstart = chunk * 63;
    const int lend   = min(lstart + 63, Lc);

    for (int l = lstart + warp; l < lend; l += 8) {
        float qr[36];
        const float4* qp = (const float4*)&g_qf[(bh * Lc + l) * DIMc];
#pragma unroll
        for (int c = 0; c < 9; c++) {
            float4 t = qp[c];
            qr[c * 4 + 0] = t.x; qr[c * 4 + 1] = t.y;
            qr[c * 4 + 2] = t.z; qr[c * 4 + 3] = t.w;
        }
        float mx = -3.4e38f;
        float sm = 0.0f;
#pragma unroll
        for (int jj = 0; jj < 8; jj++) {
            int j = lane + jj * 32;
            if (j < KSc) {
                int idx = ik[l * KSc + j];
                const float* kp = &ks[idx * 37];
                float accd = 0.0f;
#pragma unroll
                for (int d = 0; d < 36; d++) accd += qr[d] * kp[d];
                mx = fmaxf(mx, accd);
                sm += accd;
            }
        }
#pragma unroll
        for (int o = 16; o; o >>= 1) {
            mx = fmaxf(mx, __shfl_xor_sync(0xffffffffu, mx, o));
            sm += __shfl_xor_sync(0xffffffffu, sm, o);
        }
        if (lane == 0) g_measure[bh * Lc + l] = mx - sm * (1.0f / (float)Lc);
    }
}

// ---------------------------------------------------------------------------
// TopK: per bh, top-250 of 1000 measures via bitonic sort of packed u64 keys.
// key = (orderable_float << 32) | ~index  -> descending sort gives exact
// jax.lax.top_k semantics (value desc, index asc on ties).
// ---------------------------------------------------------------------------
__global__ void __launch_bounds__(512) topk_kernel()
{
    __shared__ unsigned long long keys[1024];
    const int bh  = blockIdx.x;
    const int tid = threadIdx.x;

    for (int i = tid; i < 1024; i += 512) {
        unsigned long long kv = 0ULL;
        if (i < Lc) {
            float f = g_measure[bh * Lc + i];
            unsigned u = __float_as_uint(f);
            u = (u & 0x80000000u) ? ~u : (u | 0x80000000u);
            kv = ((unsigned long long)u << 32) | (unsigned)(~i);
        }
        keys[i] = kv;
    }
    __syncthreads();

    for (int k = 2; k <= 1024; k <<= 1) {
        for (int j = k >> 1; j > 0; j >>= 1) {
#pragma unroll
            for (int w = 0; w < 2; w++) {
                int i   = tid + w * 512;
                int ixj = i ^ j;
                if (ixj > i) {
                    bool descend = ((i & k) == 0);
                    unsigned long long a = keys[i];
                    unsigned long long b = keys[ixj];
                    bool sw = descend ? (a < b) : (a > b);
                    if (sw) { keys[i] = b; keys[ixj] = a; }
                }
            }
            __syncthreads();
        }
    }

    if (tid < NQc) {
        unsigned low = (unsigned)keys[tid];
        g_idxq[bh * NQc + tid] = (int)(~low);
    }
}

// ---------------------------------------------------------------------------
// Selected-query sim GEMM: sim[bh][q][k] = (1/6) * q_sel . k
// block: 64 queries x 64 keys, K=36 in smem. grid (16 kt, 4 qt, 16 bh).
// ---------------------------------------------------------------------------
__global__ void __launch_bounds__(256) sim_kernel()
{
    __shared__ float Qs[36][68];
    __shared__ float Ks[36][68];
    const int bh = blockIdx.z;
    const int n0 = blockIdx.x * 64;
    const int m0 = blockIdx.y * 64;
    const int tid = threadIdx.x;

    for (int i = tid; i < 64 * 36; i += 256) {
        int qi = i / 36;
        int d  = i - qi * 36;
        float qv = 0.0f;
        int q = m0 + qi;
        if (q < NQc) {
            int row = g_idxq[bh * NQc + q];
            qv = g_qf[(bh * Lc + row) * DIMc + d];
        }
        Qs[d][qi] = qv;
        int kx = n0 + qi;
        Ks[d][qi] = (kx < Lc) ? g_kf[(bh * Lc + kx) * DIMc + d] : 0.0f;
    }
    __syncthreads();

    const int tx = tid & 15;
    const int ty = tid >> 4;
    float acc[4][4];
#pragma unroll
    for (int i = 0; i < 4; i++)
#pragma unroll
        for (int j = 0; j < 4; j++) acc[i][j] = 0.0f;

#pragma unroll
    for (int d = 0; d < 36; d++) {
        float4 av4 = *(const float4*)&Qs[d][ty * 4];
        float4 bv4 = *(const float4*)&Ks[d][tx * 4];
        float ar[4] = {av4.x, av4.y, av4.z, av4.w};
        float br[4] = {bv4.x, bv4.y, bv4.z, bv4.w};
#pragma unroll
        for (int i = 0; i < 4; i++)
#pragma unroll
            for (int j = 0; j < 4; j++) acc[i][j] += ar[i] * br[j];
    }

#pragma unroll
    for (int i = 0; i < 4; i++) {
        int q = m0 + ty * 4 + i;
        if (q >= NQc) continue;
#pragma unroll
        for (int j = 0; j < 4; j++) {
            int kx = n0 + tx * 4 + j;
            if (kx >= Lc) continue;
            g_sim[(bh * NQc + q) * Lc + kx] = acc[i][j] * (1.0f / 6.0f);
        }
    }
}

// ---------------------------------------------------------------------------
// Row softmax over 1000 keys, in place in g_sim. grid (250, 16), 256 threads.
// ---------------------------------------------------------------------------
__global__ void __launch_bounds__(256) softmax_kernel()
{
    const int bh = blockIdx.y;
    const int q  = blockIdx.x;
    float* row = &g_sim[(bh * NQc + q) * Lc];
    const int tid = threadIdx.x;
    __shared__ float red[8];
    __shared__ float s_m, s_inv;

    float mx = -3.4e38f;
    for (int j = tid; j < Lc; j += 256) mx = fmaxf(mx, row[j]);
#pragma unroll
    for (int o = 16; o; o >>= 1) mx = fmaxf(mx, __shfl_xor_sync(0xffffffffu, mx, o));
    if ((tid & 31) == 0) red[tid >> 5] = mx;
    __syncthreads();
    if (tid == 0) {
        float t = red[0];
        for (int i = 1; i < 8; i++) t = fmaxf(t, red[i]);
        s_m = t;
    }
    __syncthreads();

    float sum = 0.0f;
    for (int j = tid; j < Lc; j += 256) {
        float e = __expf(row[j] - s_m);
        row[j] = e;
        sum += e;
    }
#pragma unroll
    for (int o = 16; o; o >>= 1) sum += __shfl_xor_sync(0xffffffffu, sum, o);
    if ((tid & 31) == 0) red[tid >> 5] = sum;
    __syncthreads();
    if (tid == 0) {
        float t = 0.0f;
        for (int i = 0; i < 8; i++) t += red[i];
        s_inv = 1.0f / t;
    }
    __syncthreads();

    float inv = s_inv;
    for (int j = tid; j < Lc; j += 256) row[j] *= inv;
}

// ---------------------------------------------------------------------------
// V mean per (bh), deterministic tree reduction. grid 16, 256 threads.
// ---------------------------------------------------------------------------
__global__ void __launch_bounds__(256) vmean_kernel()
{
    const int bh  = blockIdx.x;
    const int tid = threadIdx.x;
    float acc[36];
#pragma unroll
    for (int d = 0; d < 36; d++) acc[d] = 0.0f;

    for (int l = tid; l < Lc; l += 256) {
        const float* vp = &g_vf[(bh * Lc + l) * DIMc];
#pragma unroll
        for (int d = 0; d < 36; d++) acc[d] += vp[d];
    }
#pragma unroll
    for (int d = 0; d < 36; d++) {
#pragma unroll
        for (int o = 16; o; o >>= 1) acc[d] += __shfl_xor_sync(0xffffffffu, acc[d], o);
    }
    __shared__ float sm[8][36];
    if ((tid & 31) == 0) {
        int w = tid >> 5;
#pragma unroll
        for (int d = 0; d < 36; d++) sm[w][d] = acc[d];
    }
    __syncthreads();
    if (tid < 36) {
        float t = 0.0f;
#pragma unroll
        for (int w = 0; w < 8; w++) t += sm[w][tid];
        g_vmean[bh * DIMc + tid] = t * (1.0f / (float)Lc);
    }
}

// Fill attn output with per-head mean(V)
__global__ void __launch_bounds__(256) fill_kernel()
{
    int i = blockIdx.x * 256 + threadIdx.x;
    if (i >= Bc * Lc * Dc) return;
    int d  = i % Dc;
    int bl = i / Dc;
    int b  = bl / Lc;
    int hh = d / 36;
    int dd = d - hh * 36;
    g_attn[i] = g_vmean[(b * Hc + hh) * DIMc + dd];
}

// ---------------------------------------------------------------------------
// AV GEMM: out_sel[250,36] = P[250,1000] @ V[1000,36], split-K=2 (determin.)
// grid (4 qt, 16 bh, 2 split), 144 threads, 4x4 tiles.
// ---------------------------------------------------------------------------
__global__ void __launch_bounds__(144) av_kernel()
{
    __shared__ float Ps[16][68];
    __shared__ float Vs[16][40];
    const int m0    = blockIdx.x * 64;
    const int bh    = blockIdx.y;
    const int split = blockIdx.z;
    const int tid   = threadIdx.x;
    const int tx = tid % 16;   // q quad
    const int ty = tid / 16;   // d quad (0..8)

    float acc[4][4];
#pragma unroll
    for (int i = 0; i < 4; i++)
#pragma unroll
        for (int j = 0; j < 4; j++) acc[i][j] = 0.0f;

    for (int kt = 0; kt < 32; kt++) {
        int k0 = split * 512 + kt * 16;
        for (int i = tid; i < 1024; i += 144) {
            int kk = i & 15;
            int qi = i >> 4;
            int q = m0 + qi, k = k0 + kk;
            Ps[kk][qi] = (q < NQc && k < Lc) ? g_sim[(bh * NQc + q) * Lc + k] : 0.0f;
        }
        for (int i = tid; i < 16 * 36; i += 144) {
            int d  = i % 36;
            int kk = i / 36;
            int k = k0 + kk;
            Vs[kk][d] = (k < Lc) ? g_vf[(bh * Lc + k) * DIMc + d] : 0.0f;
        }
        __syncthreads();
#pragma unroll
        for (int kk = 0; kk < 16; kk++) {
            float4 pv4 = *(const float4*)&Ps[kk][tx * 4];
            float4 vv4 = *(const float4*)&Vs[kk][ty * 4];
            float pr[4] = {pv4.x, pv4.y, pv4.z, pv4.w};
            float vr[4] = {vv4.x, vv4.y, vv4.z, vv4.w};
#pragma unroll
            for (int i = 0; i < 4; i++)
#pragma unroll
                for (int j = 0; j < 4; j++) acc[i][j] += pr[i] * vr[j];
        }
        __syncthreads();
    }

#pragma unroll
    for (int i = 0; i < 4; i++) {
        int q = m0 + tx * 4 + i;
        if (q >= NQc) continue;
#pragma unroll
        for (int j = 0; j < 4; j++) {
            int d = ty * 4 + j;
            g_av[((split * BHc + bh) * NQc + q) * DIMc + d] = acc[i][j];
        }
    }
}

// Scatter active-query outputs into g_attn (sum of split-k slabs)
__global__ void __launch_bounds__(256) scatter_kernel()
{
    int i = blockIdx.x * 256 + threadIdx.x;
    if (i >= BHc * NQc * DIMc) return;
    int d = i % DIMc;
    int t = i / DIMc;
    int q  = t % NQc;
    int bh = t / NQc;
    int l = g_idxq[bh * NQc + q];
    float val = g_av[((0 * BHc + bh) * NQc + q) * DIMc + d]
              + g_av[((1 * BHc + bh) * NQc + q) * DIMc + d];
    int b = bh >> 3;
    int h = bh & 7;
    g_attn[(b * Lc + l) * Dc + h * 36 + d] = val;
}

// ---------------------------------------------------------------------------
// LayerNorm over D=288: out = LN(a + b). WHICH 0: a=x(param), out=g_h1f.
// WHICH 1: a=g_f2f, b=g_h1f, out=param. grid 2000, 288 threads.
// ---------------------------------------------------------------------------
template <int WHICH>
__global__ void __launch_bounds__(288) ln_kernel(
    const float* __restrict__ xin, float* __restrict__ oout,
    const float* __restrict__ gg, const float* __restrict__ bb)
{
    const int r = blockIdx.x;
    const int d = threadIdx.x;
    const int base = r * Dc;

    float v;
    if (WHICH == 0) v = xin[base + d] + g_attn[base + d];
    else            v = g_f2f[base + d] + g_h1f[base + d];

    __shared__ float red[9];
    __shared__ float s_mu, s_rs;

    float s = v;
#pragma unroll
    for (int o = 16; o; o >>= 1) s += __shfl_xor_sync(0xffffffffu, s, o);
    if ((d & 31) == 0) red[d >> 5] = s;
    __syncthreads();
    if (d == 0) {
        float t = 0.0f;
        for (int i = 0; i < 9; i++) t += red[i];
        s_mu = t * (1.0f / (float)Dc);
    }
    __syncthreads();

    float dv = v - s_mu;
    float qv = dv * dv;
#pragma unroll
    for (int o = 16; o; o >>= 1) qv += __shfl_xor_sync(0xffffffffu, qv, o);
    if ((d & 31) == 0) red[d >> 5] = qv;
    __syncthreads();
    if (d == 0) {
        float t = 0.0f;
        for (int i = 0; i < 9; i++) t += red[i];
        s_rs = rsqrtf(t * (1.0f / (float)Dc) + 1e-5f);
    }
    __syncthreads();

    float outv = dv * s_rs * gg[d] + bb[d];
    if (WHICH == 0) g_h1f[base + d] = outv;
    else            oout[base + d]  = outv;
}

// ---------------------------------------------------------------------------
extern "C" void kernel_launch(void* const* d_in, const int* in_sizes, int n_in,
                              void* d_out, int out_size)
{
    (void)in_sizes; (void)n_in; (void)out_size;
    const float* x   = (const float*)d_in[0];
    const int*   ik  = (const int*)d_in[1];
    const float* Wq  = (const float*)d_in[2];
    const float* bq  = (const float*)d_in[3];
    const float* Wk  = (const float*)d_in[4];
    const float* bk  = (const float*)d_in[5];
    const float* Wv  = (const float*)d_in[6];
    const float* bv  = (const float*)d_in[7];
    const float* W1  = (const float*)d_in[8];
    const float* b1  = (const float*)d_in[9];
    const float* W2  = (const float*)d_in[10];
    const float* b2  = (const float*)d_in[11];
    const float* g1  = (const float*)d_in[12];
    const float* be1 = (const float*)d_in[13];
    const float* g2  = (const float*)d_in[14];
    const float* be2 = (const float*)d_in[15];
    float* out = (float*)d_out;

    const int measure_smem = Lc * 37 * (int)sizeof(float);  // 148 KB
    cudaFuncSetAttribute(measure_kernel,
                         cudaFuncAttributeMaxDynamicSharedMemorySize, measure_smem);

    // 1) QKV projections
    gemm_tiled<0><<<dim3((864 + 63) / 64, (Mrows + 63) / 64), 256>>>(
        x, Mrows, 864, Dc, Wq, Wk, Wv, bq, bk, bv);

    // 2) sparsity measure
    measure_kernel<<<dim3(16, BHc), 256, measure_smem>>>(ik);

    // 3) top-250 active queries per (b,h)
    topk_kernel<<<BHc, 512>>>();

    // 4) sim for selected queries
    sim_kernel<<<dim3(16, 4, BHc), 256>>>();

    // 5) softmax rows
    softmax_kernel<<<dim3(NQc, BHc), 256>>>();

    // 6) mean(V) + lazy fill
    vmean_kernel<<<BHc, 256>>>();
    fill_kernel<<<(Bc * Lc * Dc + 255) / 256, 256>>>();

    // 7) attn @ V (split-k = 2), then scatter active outputs
    av_kernel<<<dim3(4, BHc, 2), 144>>>();
    scatter_kernel<<<(BHc * NQc * DIMc + 255) / 256, 256>>>();

    // 8) residual + LN1
    ln_kernel<0><<<Mrows, 288>>>(x, nullptr, g1, be1);

    // 9) FFN (exact GELU both layers)
    gemm_tiled<1><<<dim3((DFFc + 63) / 64, (Mrows + 63) / 64), 256>>>(
        nullptr, Mrows, DFFc, Dc, W1, nullptr, nullptr, nullptr, b1, nullptr);
    gemm_tiled<2><<<dim3((Dc + 63) / 64, (Mrows + 63) / 64), 256>>>(
        nullptr, Mrows, Dc, DFFc, W2, nullptr, nullptr, nullptr, b2, nullptr);

    // 10) residual + LN2 -> output
    ln_kernel<1><<<Mrows, 288>>>(nullptr, out, g2, be2);
}